// round 5
// baseline (speedup 1.0000x reference)
#include <cuda_runtime.h>

#define B  32
#define L  1024
#define D  512
#define NN 512

// 8 partial-sum planes of sum_l(i - j) over L-eighths: [8][B][D]
__device__ float g_part[8 * B * D];
// DCE-defeating sink for the W prefetch
__device__ float g_sink;

// ---------------------------------------------------------------------------
// Kernel 1: part[lo][b][d] = sum_{l in eighth lo} (i[b,l,d] - j[b,l,d])
// Grid: B(32) * dt(4 tiles of 128 floats) * lo(8 L-eighths) = 1024 blocks.
// Block: 256 threads, <=32 regs -> 8 blocks/SM -> ALL 1024 blocks resident
// (no wave quantization). dq = tid&31: a full warp's LDG.128 covers one
// contiguous 512B row segment. lg = tid>>5: 8 l-groups x 16 rows.
// i/j streamed with __ldcs (evict-first) so W survives in L2.
// Side job: prefetch W (1 MB) into L2 for kernel 2.
// ---------------------------------------------------------------------------
__global__ void __launch_bounds__(256, 8) mean_diff_kernel(
    const float* __restrict__ gi, const float* __restrict__ gj,
    const float* __restrict__ W)
{
    const int blk = blockIdx.x;
    const int b   = blk >> 5;         // batch
    const int r   = blk & 31;
    const int dt  = r >> 3;           // 128-float d tile (4 per D)
    const int lo  = r & 7;            // L eighth
    const int tid = threadIdx.x;
    const int dq  = tid & 31;         // float4 within 128-float tile
    const int lg  = tid >> 5;         // l-group (8 groups x 16 rows)

    // --- W prefetch: 1024 blocks x 64 float4 = 1 MB into L2 ---
    if (tid < 64) {
        float4 w = __ldcg(((const float4*)W) + blk * 64 + tid);
        float t = w.x + w.y + w.z + w.w;
        if (__float_as_int(t) == 0x7f800001)  // never true in practice
            g_sink = t;
    }

    const int rowq = D / 4;           // 128 float4 per row
    const float4* pi = (const float4*)(gi + (size_t)b * L * D) + dt * 32 + dq;
    const float4* pj = (const float4*)(gj + (size_t)b * L * D) + dt * 32 + dq;

    const int l0 = lo * 128 + lg * 16;
    float4 acc = make_float4(0.f, 0.f, 0.f, 0.f);
    #pragma unroll
    for (int rr = 0; rr < 16; rr++) {
        size_t off = (size_t)(l0 + rr) * rowq;
        float4 a = __ldcs(pi + off);
        float4 c = __ldcs(pj + off);
        acc.x += a.x - c.x;
        acc.y += a.y - c.y;
        acc.z += a.z - c.z;
        acc.w += a.w - c.w;
    }

    __shared__ float4 s[256];
    s[tid] = acc;
    __syncthreads();

    #pragma unroll
    for (int stride = 128; stride >= 32; stride >>= 1) {
        if (tid < stride) {
            float4 o = s[tid + stride];
            s[tid].x += o.x; s[tid].y += o.y; s[tid].z += o.z; s[tid].w += o.w;
        }
        __syncthreads();
    }

    if (tid < 32)
        ((float4*)(g_part + lo * B * D + b * D + dt * 128))[tid] = s[tid];
}

// ---------------------------------------------------------------------------
// Kernel 2: md[b,d] = (1/L) * sum_lo part[lo][b][d]
//           u[b,n]  = sum_d md[b,d] * W[d,n]
//           out[b,n] = 0.5*(relu(u + bias[n]) + relu(bias[n] - u))
// Grid: 8 batch-groups(4 batches each) * 8 n-tiles(64) = 64 blocks x 512 thr.
// Each W element read ONCE per block and reused in 4 FMAs (4 batches) ->
// W L2 traffic 8MB total (was 32MB). nloc=tid&63, dg=tid>>6 (8 d-groups).
// ---------------------------------------------------------------------------
__global__ void __launch_bounds__(512) gemv_combine_kernel(
    const float* __restrict__ W, const float* __restrict__ bias,
    float* __restrict__ out)
{
    const int blk  = blockIdx.x;
    const int bg   = blk >> 3;        // batch group (4 batches)
    const int nt   = blk & 7;         // 64-wide n tile
    const int b0   = bg * 4;
    const int tid  = threadIdx.x;
    const int nloc = tid & 63;
    const int dg   = tid >> 6;        // d-group 0..7

    __shared__ float smd[4][D];
    {
        const float inv = 1.0f / (float)L;
        #pragma unroll
        for (int bb = 0; bb < 4; bb++) {
            const float* p = g_part + (b0 + bb) * D + tid;
            float v = 0.f;
            #pragma unroll
            for (int pl = 0; pl < 8; pl++)
                v += p[pl * B * D];
            smd[bb][tid] = v * inv;
        }
    }
    __syncthreads();

    const int n = nt * 64 + nloc;
    const float* Wp = W + (size_t)(dg * 64) * NN + n;

    float u0 = 0.f, u1 = 0.f, u2 = 0.f, u3 = 0.f;
    #pragma unroll
    for (int d = 0; d < 64; d++) {
        float w = __ldg(Wp + (size_t)d * NN);
        int di = dg * 64 + d;
        u0 = fmaf(smd[0][di], w, u0);
        u1 = fmaf(smd[1][di], w, u1);
        u2 = fmaf(smd[2][di], w, u2);
        u3 = fmaf(smd[3][di], w, u3);
    }

    __shared__ float su[4][512];
    su[0][tid] = u0; su[1][tid] = u1; su[2][tid] = u2; su[3][tid] = u3;
    __syncthreads();

    if (tid < 256) {
        const int bb = tid >> 6;      // batch within group
        const int nn = tid & 63;
        float t = 0.f;
        #pragma unroll
        for (int g = 0; g < 8; g++)
            t += su[bb][g * 64 + nn];
        float bv = bias[nt * 64 + nn];
        out[(b0 + bb) * NN + nt * 64 + nn] =
            0.5f * (fmaxf(t + bv, 0.f) + fmaxf(bv - t, 0.f));
    }
}

extern "C" void kernel_launch(void* const* d_in, const int* in_sizes, int n_in,
                              void* d_out, int out_size)
{
    const float* gi   = (const float*)d_in[0];   // i     [B, L, D]
    const float* gj   = (const float*)d_in[1];   // j     [B, L, D]
    const float* W    = (const float*)d_in[2];   // W_agg [D, NN]
    const float* bias = (const float*)d_in[3];   // b_agg [NN]
    float* out = (float*)d_out;                  // [B, NN]

    mean_diff_kernel<<<1024, 256>>>(gi, gj, W);
    gemv_combine_kernel<<<64, 512>>>(W, bias, out);
}

// round 6
// speedup vs baseline: 1.1206x; 1.1206x over previous
#include <cuda_runtime.h>

#define B  32
#define L  1024
#define D  512
#define NN 512

// 8 partial-sum planes of sum_l(i - j) over L-eighths: [8][B][D]
__device__ float g_part[8 * B * D];
// DCE-defeating sink for the W prefetch
__device__ float g_sink;

// ---------------------------------------------------------------------------
// Kernel 1 (unchanged from R4 — measured 19.9us, ~6.4 TB/s):
// part[lo][b][d] = sum_{l in eighth lo} (i[b,l,d] - j[b,l,d])
// Grid: B(32) * dt(4 tiles of 128 floats) * lo(8 L-eighths) = 1024 blocks,
// all resident (8 blocks/SM). Full-warp 512B LDG.128 rows, __ldcs streaming.
// Side job: prefetch W (1 MB) into L2 for kernel 2.
// ---------------------------------------------------------------------------
__global__ void __launch_bounds__(256, 8) mean_diff_kernel(
    const float* __restrict__ gi, const float* __restrict__ gj,
    const float* __restrict__ W)
{
    const int blk = blockIdx.x;
    const int b   = blk >> 5;         // batch
    const int r   = blk & 31;
    const int dt  = r >> 3;           // 128-float d tile (4 per D)
    const int lo  = r & 7;            // L eighth
    const int tid = threadIdx.x;
    const int dq  = tid & 31;         // float4 within 128-float tile
    const int lg  = tid >> 5;         // l-group (8 groups x 16 rows)

    // --- W prefetch: 1024 blocks x 64 float4 = 1 MB into L2 ---
    if (tid < 64) {
        float4 w = __ldcg(((const float4*)W) + blk * 64 + tid);
        float t = w.x + w.y + w.z + w.w;
        if (__float_as_int(t) == 0x7f800001)  // never true in practice
            g_sink = t;
    }

    const int rowq = D / 4;           // 128 float4 per row
    const float4* pi = (const float4*)(gi + (size_t)b * L * D) + dt * 32 + dq;
    const float4* pj = (const float4*)(gj + (size_t)b * L * D) + dt * 32 + dq;

    const int l0 = lo * 128 + lg * 16;
    float4 acc = make_float4(0.f, 0.f, 0.f, 0.f);
    #pragma unroll
    for (int rr = 0; rr < 16; rr++) {
        size_t off = (size_t)(l0 + rr) * rowq;
        float4 a = __ldcs(pi + off);
        float4 c = __ldcs(pj + off);
        acc.x += a.x - c.x;
        acc.y += a.y - c.y;
        acc.z += a.z - c.z;
        acc.w += a.w - c.w;
    }

    __shared__ float4 s[256];
    s[tid] = acc;
    __syncthreads();

    #pragma unroll
    for (int stride = 128; stride >= 32; stride >>= 1) {
        if (tid < stride) {
            float4 o = s[tid + stride];
            s[tid].x += o.x; s[tid].y += o.y; s[tid].z += o.z; s[tid].w += o.w;
        }
        __syncthreads();
    }

    if (tid < 32)
        ((float4*)(g_part + lo * B * D + b * D + dt * 128))[tid] = s[tid];
}

// ---------------------------------------------------------------------------
// Kernel 2: md[b,d] = (1/L) * sum_lo part[lo][b][d]
//           u[b,n]  = sum_d md[b,d] * W[d,n]
//           out[b,n] = 0.5*(relu(u + bias[n]) + relu(bias[n] - u))
// Grid: 16 batch-pairs * 16 n-tiles(32 wide) = 256 blocks x 512 threads
// (R3's parallelism). Thread map: nloc = tid&31, dg = tid>>5 (16 d-groups
// of 32 rows). Per thread: 32 fully-unrolled independent W loads (high MLP,
// half the dependent chain of R3), each reused for 2 batches.
// W L2 traffic: 256 blocks * 64KB = 16 MB (half of R3).
// ---------------------------------------------------------------------------
__global__ void __launch_bounds__(512) gemv_combine_kernel(
    const float* __restrict__ W, const float* __restrict__ bias,
    float* __restrict__ out)
{
    const int blk  = blockIdx.x;
    const int bg   = blk >> 4;        // batch pair (2 batches)
    const int nt   = blk & 15;        // 32-wide n tile
    const int b0   = bg * 2;
    const int tid  = threadIdx.x;
    const int nloc = tid & 31;
    const int dg   = tid >> 5;        // d-group 0..15 (32 rows each)

    __shared__ float smd[2][D];
    {
        const float inv = 1.0f / (float)L;
        #pragma unroll
        for (int bb = 0; bb < 2; bb++) {
            const float* p = g_part + (b0 + bb) * D + tid;
            float v = 0.f;
            #pragma unroll
            for (int pl = 0; pl < 8; pl++)
                v += p[pl * B * D];
            smd[bb][tid] = v * inv;
        }
    }
    __syncthreads();

    const int n = nt * 32 + nloc;
    const float* Wp = W + (size_t)(dg * 32) * NN + n;

    float u0 = 0.f, u1 = 0.f;
    #pragma unroll
    for (int d = 0; d < 32; d++) {
        float w = __ldg(Wp + (size_t)d * NN);
        int di = dg * 32 + d;
        u0 = fmaf(smd[0][di], w, u0);
        u1 = fmaf(smd[1][di], w, u1);
    }

    __shared__ float su[2][512];
    su[0][tid] = u0;
    su[1][tid] = u1;
    __syncthreads();

    // 64 results (2 batches x 32 n) each need a 16-way partial sum.
    if (tid < 64) {
        const int bb = tid >> 5;      // batch within pair
        const int nn = tid & 31;
        float t = 0.f;
        #pragma unroll
        for (int g = 0; g < 16; g++)
            t += su[bb][g * 32 + nn];
        float bv = bias[nt * 32 + nn];
        out[(b0 + bb) * NN + nt * 32 + nn] =
            0.5f * (fmaxf(t + bv, 0.f) + fmaxf(bv - t, 0.f));
    }
}

extern "C" void kernel_launch(void* const* d_in, const int* in_sizes, int n_in,
                              void* d_out, int out_size)
{
    const float* gi   = (const float*)d_in[0];   // i     [B, L, D]
    const float* gj   = (const float*)d_in[1];   // j     [B, L, D]
    const float* W    = (const float*)d_in[2];   // W_agg [D, NN]
    const float* bias = (const float*)d_in[3];   // b_agg [NN]
    float* out = (float*)d_out;                  // [B, NN]

    mean_diff_kernel<<<1024, 256>>>(gi, gj, W);
    gemv_combine_kernel<<<256, 512>>>(W, bias, out);
}